// round 13
// baseline (speedup 1.0000x reference)
#include <cuda_runtime.h>
#include <cuda_fp16.h>
#include <cstdint>

#define S_LEN 4096
#define D_MODEL 256
#define NTHREADS 256
#define QPW 4
#define QPB 32            // 8 warps * 4 queries
#define MUFU_CHUNKS 13    // keys [0, 13*256) via f16x2 MUFU path
#define POLY_KEYS (S_LEN - MUFU_CHUNKS * 256)   // 768 keys via f32x2 poly path

typedef unsigned long long ull;

__device__ __forceinline__ float ex2f(float a) {
    float r; asm("ex2.approx.f32 %0,%1;" : "=f"(r) : "f"(a)); return r;
}
__device__ __forceinline__ __half2 u2h(uint32_t u) {
    return *reinterpret_cast<__half2*>(&u);
}
__device__ __forceinline__ __half2 negabs2(__half2 d) {
    uint32_t u = *reinterpret_cast<uint32_t*>(&d) | 0x80008000u;
    return *reinterpret_cast<__half2*>(&u);
}
// ---- f32x2 packed helpers (births packed, splits only) ----
__device__ __forceinline__ ull pk2(float lo, float hi) {
    ull r; asm("mov.b64 %0,{%1,%2};" : "=l"(r) : "f"(lo), "f"(hi)); return r;
}
__device__ __forceinline__ ull add2(ull a, ull b) {
    ull r; asm("add.rn.f32x2 %0,%1,%2;" : "=l"(r) : "l"(a), "l"(b)); return r;
}
__device__ __forceinline__ ull fma2(ull a, ull b, ull c) {
    ull r; asm("fma.rn.f32x2 %0,%1,%2,%3;" : "=l"(r) : "l"(a), "l"(b), "l"(c)); return r;
}
__device__ __forceinline__ ull ldsb64(uint32_t addr) {
    ull v; asm volatile("ld.shared.b64 %0,[%1];" : "=l"(v) : "r"(addr)); return v;
}
__device__ __forceinline__ void spltu(ull a, uint32_t& lo, uint32_t& hi) {
    asm("mov.b64 {%0,%1},%2;" : "=r"(lo), "=r"(hi) : "l"(a));
}
__device__ __forceinline__ void spltf(ull a, float& lo, float& hi) {
    asm("mov.b64 {%0,%1},%2;" : "=f"(lo), "=f"(hi) : "l"(a));
}
#define SGNM64 0x8000000080000000ULL

__global__ __launch_bounds__(NTHREADS) void dwsa_kernel(
    const float2* __restrict__ x,   // [B, S, 2] (size, height)
    const float* __restrict__ Wq,
    const float* __restrict__ Wk,
    const float* __restrict__ Wv,
    float* __restrict__ out)        // [B, S, 256]
{
    __shared__ __half2  nszh[S_LEN / 2];        // -lam2*size f16x2 (8 KB)
    __shared__ __half2  hph [S_LEN / 2];        // height f16x2     (8 KB)
    __shared__ float    nszf[POLY_KEYS];        // f32 tail keys    (3 KB)
    __shared__ float    hf  [POLY_KEYS];        // f32 tail heights (3 KB)
    __shared__ float    red[48];

    const int tid  = threadIdx.x;
    const int lane = tid & 31;
    const int warp = tid >> 5;
    const int blocks_per_batch = S_LEN / QPB;    // 128
    const int b  = blockIdx.x / blocks_per_batch;
    const int q0 = (blockIdx.x % blocks_per_batch) * QPB;

    const float LOG2E = 1.4426950408889634f;
    const float LAM2  = 0.5f * LOG2E;
    const int POLY_I0 = MUFU_CHUNKS * 128;       // float2-index where poly keys start

    // --- Stage batch; reductions in f32 ---
    const float2* xb  = x + (size_t)b * S_LEN;
    const float4* xb4 = (const float4*)xb;
    float hmax = -1e30f, hmin = 1e30f, szmax = -1e30f, szmin = 1e30f;
    int zflag = 0;
    for (int i = tid; i < S_LEN / 2; i += NTHREADS) {
        float4 v = xb4[i];                        // {sz0, h0, sz1, h1}
        float n0 = -LAM2 * v.x, n1 = -LAM2 * v.z;
        nszh[i] = __floats2half2_rn(n0, n1);
        hph [i] = __floats2half2_rn(v.y, v.w);
        if (i >= POLY_I0) {                       // f32 mirror for the poly tail
            ((float2*)nszf)[i - POLY_I0] = make_float2(n0, n1);
            ((float2*)hf  )[i - POLY_I0] = make_float2(v.y, v.w);
        }
        hmax = fmaxf(hmax, fmaxf(v.y, v.w));   hmin = fminf(hmin, fminf(v.y, v.w));
        szmax = fmaxf(szmax, fmaxf(v.x, v.z)); szmin = fminf(szmin, fminf(v.x, v.z));
        zflag |= (v.y == 0.f) | (v.w == 0.f);
    }
    float cp = Wq[tid] * Wk[tid];                 // NTHREADS == D_MODEL
    #pragma unroll
    for (int o = 16; o > 0; o >>= 1) {
        hmax  = fmaxf(hmax,  __shfl_xor_sync(0xffffffffu, hmax,  o));
        hmin  = fminf(hmin,  __shfl_xor_sync(0xffffffffu, hmin,  o));
        szmax = fmaxf(szmax, __shfl_xor_sync(0xffffffffu, szmax, o));
        szmin = fminf(szmin, __shfl_xor_sync(0xffffffffu, szmin, o));
        cp   += __shfl_xor_sync(0xffffffffu, cp, o);
    }
    if (lane == 0) {
        red[warp] = hmax; red[8+warp] = hmin; red[16+warp] = szmax;
        red[24+warp] = szmin; red[32+warp] = cp;
    }
    const int anyzero = __syncthreads_or(zflag);
    hmax = red[0]; hmin = red[8]; szmax = red[16]; szmin = red[24];
    float csum = red[32];
    #pragma unroll
    for (int w = 1; w < 8; w++) {
        hmax = fmaxf(hmax, red[w]);       hmin = fminf(hmin, red[8+w]);
        szmax = fmaxf(szmax, red[16+w]);  szmin = fminf(szmin, red[24+w]);
        csum += red[32+w];
    }
    const float c = csum * (1.0f / 16.0f);
    const float wspan = LAM2 * (szmax - szmin);

    // --- Four queries per warp ---
    float qszf_[QPW], a2f[QPW], nM2f[QPW];
    #pragma unroll
    for (int q = 0; q < QPW; q++) {
        float2 xq = xb[q0 + warp + q * 8];
        qszf_[q] = LAM2 * xq.x;
        a2f[q]   = c * xq.y * LOG2E;
        nM2f[q]  = -fmaxf(a2f[q] * hmax, a2f[q] * hmin);
    }

    float zf[QPW], rf[QPW];
    #pragma unroll
    for (int q = 0; q < QPW; q++) { zf[q] = 0.f; rf[q] = 0.f; }
    const bool fast = (!anyzero) && (wspan <= 13.0f);

    if (fast) {
        // ===== Path 1: f16x2 MUFU over chunks [0, MUFU_CHUNKS) =====
        __half2 q2h[QPW], a2h[QPW], m2h[QPW];
        #pragma unroll
        for (int q = 0; q < QPW; q++) {
            q2h[q] = __float2half2_rn(qszf_[q]);
            a2h[q] = __float2half2_rn(a2f[q]);
            m2h[q] = __float2half2_rn(nM2f[q]);
        }
        const uint4* nh4 = (const uint4*)nszh;
        const uint4* hp4 = (const uint4*)hph;

        __half2 z2[QPW], r2[QPW];
        #pragma unroll
        for (int q = 0; q < QPW; q++) { z2[q] = __float2half2_rn(0.f); r2[q] = z2[q]; }

        for (int ch = 0; ch < MUFU_CHUNKS; ch++) {
            const int j = lane + ch * 32;
            uint4 sv = nh4[j];
            uint4 hv = hp4[j];
            #pragma unroll
            for (int e = 0; e < 4; e++) {
                uint32_t su = (e == 0) ? sv.x : (e == 1) ? sv.y : (e == 2) ? sv.z : sv.w;
                uint32_t hu = (e == 0) ? hv.x : (e == 1) ? hv.y : (e == 2) ? hv.z : hv.w;
                __half2 s2 = u2h(su);
                __half2 h2 = u2h(hu);
                #pragma unroll
                for (int q = 0; q < QPW; q++) {
                    __half2 d2 = __hadd2(q2h[q], s2);
                    __half2 n2 = negabs2(d2);
                    __half2 t2 = __hfma2(a2h[q], h2, m2h[q]);
                    __half2 p2 = h2exp2(__hadd2(t2, n2));
                    z2[q] = __hadd2(z2[q], p2);
                    r2[q] = __hfma2(p2, h2, r2[q]);
                }
            }
            if ((ch & 1) || ch == MUFU_CHUNKS - 1) {     // flush every 2 chunks
                #pragma unroll
                for (int q = 0; q < QPW; q++) {
                    float2 f;
                    f = __half22float2(z2[q]); zf[q] += f.x + f.y;
                    f = __half22float2(r2[q]); rf[q] += f.x + f.y;
                    z2[q] = __float2half2_rn(0.f); r2[q] = z2[q];
                }
            }
        }

        // ===== Path 2: f32x2 poly exp2 over the 768-key tail (no MUFU) =====
        // 2^arg: rni via +-(2^23+2^22); p_bits = poly(frac)_bits + (iz<<23)
        const ull Cp   = pk2( 12582912.0f,  12582912.0f);
        const ull nCp  = pk2(-12582912.0f, -12582912.0f);
        const ull c4p  = pk2(0.00961813f, 0.00961813f);
        const ull c3p  = pk2(0.05550411f, 0.05550411f);
        const ull c2p  = pk2(0.24022651f, 0.24022651f);
        const ull c1p  = pk2(0.69314718f, 0.69314718f);
        const ull onep = pk2(1.0f, 1.0f);
        const uint32_t sa = (uint32_t)__cvta_generic_to_shared(nszf) + lane * 8;
        const uint32_t ha = (uint32_t)__cvta_generic_to_shared(hf)   + lane * 8;

        #pragma unroll
        for (int q = 0; q < QPW; q++) {
            const ull q2p = pk2(qszf_[q], qszf_[q]);
            const ull a2p = pk2(a2f[q],  a2f[q]);
            const ull m2p = pk2(nM2f[q], nM2f[q]);
            float z0 = 0.f, z1 = 0.f, r0 = 0.f, r1 = 0.f;
            #pragma unroll 4
            for (int it = 0; it < POLY_KEYS / 64; it++) {    // 12 iters, 2 keys/lane
                ull s2 = ldsb64(sa + it * 256);
                ull h2 = ldsb64(ha + it * 256);
                ull d2  = add2(q2p, s2);
                ull n2  = d2 | SGNM64;                       // -(lam2*|dsz|)
                ull t2  = fma2(a2p, h2, m2p);
                ull arg = add2(t2, n2);                      // in [-54, 0]
                ull zr  = add2(arg, Cp);                     // rni(arg) embedded
                ull tn  = add2(zr, nCp);                     // = rni(arg) as f32x2
                ull f2  = add2(arg, tn ^ SGNM64);            // frac in [-0.5, 0.5]
                ull pp  = fma2(f2, c4p, c3p);
                pp = fma2(f2, pp, c2p);
                pp = fma2(f2, pp, c1p);
                pp = fma2(f2, pp, onep);                     // 2^frac
                uint32_t iz0, iz1, pb0, pb1;
                spltu(zr, iz0, iz1);
                spltu(pp, pb0, pb1);
                float p0 = __int_as_float(pb0 + (iz0 << 23));  // * 2^int
                float p1 = __int_as_float(pb1 + (iz1 << 23));
                float h0, h1;
                spltf(h2, h0, h1);
                z0 += p0; z1 += p1;
                r0 = fmaf(p0, h0, r0);
                r1 = fmaf(p1, h1, r1);
            }
            zf[q] += z0 + z1;
            rf[q] += r0 + r1;
        }
    } else {
        // ===== Exact f32 fallback (key-masked), reads global x =====
        for (int t = lane; t < S_LEN; t += 32) {
            float2 kx = xb[t];
            float ht = kx.y;
            float nszt = -LAM2 * kx.x;
            #pragma unroll
            for (int q = 0; q < QPW; q++) {
                float d = qszf_[q] + nszt;
                float p = ex2f(fmaf(a2f[q], ht, nM2f[q]) - fabsf(d));
                if (ht == 0.f) p = 0.f;
                zf[q] += p; rf[q] = fmaf(p, ht, rf[q]);
            }
        }
    }

    const float4* wv4 = (const float4*)Wv;
    #pragma unroll
    for (int q = 0; q < QPW; q++) {
        float z = zf[q], r = rf[q];
        #pragma unroll
        for (int o = 16; o > 0; o >>= 1) {
            z += __shfl_xor_sync(0xffffffffu, z, o);
            r += __shfl_xor_sync(0xffffffffu, r, o);
        }
        const float val = (z > 0.f) ? __fdividef(r, z) : 0.f;
        const int s = q0 + warp + q * 8;
        float4* o4 = (float4*)(out + ((size_t)b * S_LEN + s) * D_MODEL);
        #pragma unroll
        for (int k = 0; k < 2; k++) {
            float4 w = wv4[lane * 2 + k];
            o4[lane * 2 + k] = make_float4(val * w.x, val * w.y, val * w.z, val * w.w);
        }
    }
}

extern "C" void kernel_launch(void* const* d_in, const int* in_sizes, int n_in,
                              void* d_out, int out_size) {
    const float2* x  = (const float2*)d_in[0];
    const float*  Wq = (const float*)d_in[1];
    const float*  Wk = (const float*)d_in[2];
    const float*  Wv = (const float*)d_in[3];
    float* out = (float*)d_out;

    const int B = in_sizes[0] / (S_LEN * 2);
    const int grid = B * (S_LEN / QPB);
    dwsa_kernel<<<grid, NTHREADS>>>(x, Wq, Wk, Wv, out);
}

// round 14
// speedup vs baseline: 1.3234x; 1.3234x over previous
#include <cuda_runtime.h>
#include <cuda_fp16.h>
#include <cstdint>

#define S_LEN 4096
#define D_MODEL 256
#define NTHREADS 256
#define QPB 16

__device__ __forceinline__ float ex2f(float a) {
    float r; asm("ex2.approx.f32 %0,%1;" : "=f"(r) : "f"(a)); return r;
}
__device__ __forceinline__ __half2 u2h(uint32_t u) {
    return *reinterpret_cast<__half2*>(&u);
}
// Single-instruction packed exp2: ex2.approx.f16x2 (one MUFU op, 2 halves)
__device__ __forceinline__ __half2 ex2h2(__half2 a) {
    __half2 r;
    asm("ex2.approx.f16x2 %0,%1;"
        : "=r"(*reinterpret_cast<uint32_t*>(&r))
        : "r"(*reinterpret_cast<const uint32_t*>(&a)));
    return r;
}

__global__ __launch_bounds__(NTHREADS) void dwsa_kernel(
    const float2* __restrict__ x,   // [B, S, 2] (size, height)
    const float* __restrict__ Wq,
    const float* __restrict__ Wk,
    const float* __restrict__ Wv,
    float* __restrict__ out)        // [B, S, 256]
{
    __shared__ __half2  nszh[S_LEN / 2];   // -lam2*size f16x2 (8 KB)
    __shared__ __half2  hph [S_LEN / 2];   // height f16x2     (8 KB)
    __shared__ float    red[48];

    const int tid  = threadIdx.x;
    const int lane = tid & 31;
    const int warp = tid >> 5;
    const int blocks_per_batch = S_LEN / QPB;
    const int b  = blockIdx.x / blocks_per_batch;
    const int q0 = (blockIdx.x % blocks_per_batch) * QPB;

    const float LOG2E = 1.4426950408889634f;
    const float LAM2  = 0.5f * LOG2E;

    // --- Stage batch into packed half2 smem; reductions in f32 ---
    const float2* xb  = x + (size_t)b * S_LEN;
    const float4* xb4 = (const float4*)xb;
    float hmax = -1e30f, hmin = 1e30f, szmax = -1e30f, szmin = 1e30f;
    int zflag = 0;
    for (int i = tid; i < S_LEN / 2; i += NTHREADS) {
        float4 v = xb4[i];                        // {sz0, h0, sz1, h1}
        nszh[i] = __floats2half2_rn(-LAM2 * v.x, -LAM2 * v.z);
        hph [i] = __floats2half2_rn(v.y, v.w);
        hmax = fmaxf(hmax, fmaxf(v.y, v.w));   hmin = fminf(hmin, fminf(v.y, v.w));
        szmax = fmaxf(szmax, fmaxf(v.x, v.z)); szmin = fminf(szmin, fminf(v.x, v.z));
        zflag |= (v.y == 0.f) | (v.w == 0.f);
    }
    float cp = Wq[tid] * Wk[tid];                 // NTHREADS == D_MODEL
    #pragma unroll
    for (int o = 16; o > 0; o >>= 1) {
        hmax  = fmaxf(hmax,  __shfl_xor_sync(0xffffffffu, hmax,  o));
        hmin  = fminf(hmin,  __shfl_xor_sync(0xffffffffu, hmin,  o));
        szmax = fmaxf(szmax, __shfl_xor_sync(0xffffffffu, szmax, o));
        szmin = fminf(szmin, __shfl_xor_sync(0xffffffffu, szmin, o));
        cp   += __shfl_xor_sync(0xffffffffu, cp, o);
    }
    if (lane == 0) {
        red[warp] = hmax; red[8+warp] = hmin; red[16+warp] = szmax;
        red[24+warp] = szmin; red[32+warp] = cp;
    }
    const int anyzero = __syncthreads_or(zflag);
    hmax = red[0]; hmin = red[8]; szmax = red[16]; szmin = red[24];
    float csum = red[32];
    #pragma unroll
    for (int w = 1; w < 8; w++) {
        hmax = fmaxf(hmax, red[w]);       hmin = fminf(hmin, red[8+w]);
        szmax = fmaxf(szmax, red[16+w]);  szmin = fminf(szmin, red[24+w]);
        csum += red[32+w];
    }
    const float c = csum * (1.0f / 16.0f);
    const float wspan = LAM2 * (szmax - szmin);

    // --- Two queries per warp; params read directly from global (L1-hot) ---
    const int sA = q0 + warp, sB = q0 + warp + 8;
    const float2 xA = xb[sA], xB = xb[sB];
    const float qszA = LAM2 * xA.x, hsA = xA.y;
    const float qszB = LAM2 * xB.x, hsB = xB.y;
    const float a2A  = c * hsA * LOG2E;
    const float a2B  = c * hsB * LOG2E;
    const float nM2A = -fmaxf(a2A * hmax, a2A * hmin);
    const float nM2B = -fmaxf(a2B * hmax, a2B * hmin);

    float zv[2], rv[2];
    const bool fast = (!anyzero) && (wspan <= 13.0f);

    if (fast) {
        // ===== Full-half2 path; ex2.approx.f16x2 emitted directly =====
        const __half2 qA2 = __float2half2_rn(qszA);
        const __half2 aA2 = __float2half2_rn(a2A);
        const __half2 mA2 = __float2half2_rn(nM2A);
        const __half2 qB2 = __float2half2_rn(qszB);
        const __half2 aB2 = __float2half2_rn(a2B);
        const __half2 mB2 = __float2half2_rn(nM2B);
        const uint4* nh4 = (const uint4*)nszh;   // 512 uint4 = 16 chunks x 32 lanes
        const uint4* hp4 = (const uint4*)hph;

        float zA = 0.f, rA = 0.f, zB = 0.f, rB = 0.f;
        for (int g = 0; g < 8; g++) {            // 8 groups x 2 chunks; flush per group
            __half2 z2A = __float2half2_rn(0.f), r2A = __float2half2_rn(0.f);
            __half2 z2B = __float2half2_rn(0.f), r2B = __float2half2_rn(0.f);
            #pragma unroll
            for (int ci = 0; ci < 2; ci++) {
                const int j = lane + (g * 2 + ci) * 32;
                uint4 sv = nh4[j];               // 4 half2 = 8 keys (-lam2*sz)
                uint4 hv = hp4[j];               // 4 half2 = 8 heights
                #pragma unroll
                for (int e = 0; e < 4; e++) {
                    uint32_t su = (e == 0) ? sv.x : (e == 1) ? sv.y : (e == 2) ? sv.z : sv.w;
                    uint32_t hu = (e == 0) ? hv.x : (e == 1) ? hv.y : (e == 2) ? hv.z : hv.w;
                    __half2 s2 = u2h(su);
                    __half2 h2 = u2h(hu);
                    // query A
                    {
                        __half2 d2 = __hadd2(qA2, s2);
                        __half2 t2 = __hfma2(aA2, h2, mA2);
                        __half2 p2 = ex2h2(__hsub2(t2, __habs2(d2)));  // habs folds as |src|
                        z2A = __hadd2(z2A, p2);
                        r2A = __hfma2(p2, h2, r2A);
                    }
                    // query B
                    {
                        __half2 d2 = __hadd2(qB2, s2);
                        __half2 t2 = __hfma2(aB2, h2, mB2);
                        __half2 p2 = ex2h2(__hsub2(t2, __habs2(d2)));
                        z2B = __hadd2(z2B, p2);
                        r2B = __hfma2(p2, h2, r2B);
                    }
                }
            }
            float2 f;
            f = __half22float2(z2A); zA += f.x + f.y;
            f = __half22float2(r2A); rA += f.x + f.y;
            f = __half22float2(z2B); zB += f.x + f.y;
            f = __half22float2(r2B); rB += f.x + f.y;
        }
        zv[0] = zA; rv[0] = rA; zv[1] = zB; rv[1] = rB;
    } else {
        // ===== Exact f32 fallback (key-masked), reads global x (L1/L2-hot) =====
        #pragma unroll
        for (int qi = 0; qi < 2; qi++) {
            const float qsz = qi ? qszB : qszA;
            const float a2  = qi ? a2B  : a2A;
            const float nM2 = qi ? nM2B : nM2A;
            float zz = 0.f, rr = 0.f;
            for (int t = lane; t < S_LEN; t += 32) {
                float2 kx = xb[t];
                float ht = kx.y;
                float d  = qsz - LAM2 * kx.x;
                float p  = ex2f(fmaf(a2, ht, nM2) - fabsf(d));
                if (ht == 0.f) p = 0.f;
                zz += p; rr = fmaf(p, ht, rr);
            }
            zv[qi] = zz; rv[qi] = rr;
        }
    }

    const float4* wv4 = (const float4*)Wv;
    #pragma unroll
    for (int qi = 0; qi < 2; qi++) {
        float z = zv[qi], r = rv[qi];
        #pragma unroll
        for (int o = 16; o > 0; o >>= 1) {
            z += __shfl_xor_sync(0xffffffffu, z, o);
            r += __shfl_xor_sync(0xffffffffu, r, o);
        }
        const float val = (z > 0.f) ? __fdividef(r, z) : 0.f;
        const int s = q0 + warp + qi * 8;
        float4* o4 = (float4*)(out + ((size_t)b * S_LEN + s) * D_MODEL);
        #pragma unroll
        for (int k = 0; k < 2; k++) {
            float4 w = wv4[lane * 2 + k];
            o4[lane * 2 + k] = make_float4(val * w.x, val * w.y, val * w.z, val * w.w);
        }
    }
}

extern "C" void kernel_launch(void* const* d_in, const int* in_sizes, int n_in,
                              void* d_out, int out_size) {
    const float2* x  = (const float2*)d_in[0];
    const float*  Wq = (const float*)d_in[1];
    const float*  Wk = (const float*)d_in[2];
    const float*  Wv = (const float*)d_in[3];
    float* out = (float*)d_out;

    const int B = in_sizes[0] / (S_LEN * 2);
    const int grid = B * (S_LEN / QPB);
    dwsa_kernel<<<grid, NTHREADS>>>(x, Wq, Wk, Wv, out);
}